// round 3
// baseline (speedup 1.0000x reference)
#include <cuda_runtime.h>
#include <cuda_bf16.h>

// Problem constants (from reference): N=50000, E=800000, D=128, H=4, C=32
#define NMAX 50048
#define E2MAX 860000

// Scratch (static __device__ — no allocations allowed)
__device__ float g_h[NMAX * 128];      // post LN+ReLU features
__device__ float g_hnorm[NMAX];        // ||h_i||_2
__device__ float g_xlr[NMAX * 256];    // [xl | xr] packed per node
__device__ int   g_count[NMAX];
__device__ int   g_rowoff[NMAX + 1];
__device__ int   g_cursor[NMAX];
__device__ int   g_csrc[E2MAX];        // CSR (by dst) of source node ids

// ---------------------------------------------------------------------------
// Kernel 1: LayerNorm -> ReLU, plus ||h||_2 per node. One block (128 thr) / node.
// ---------------------------------------------------------------------------
__global__ __launch_bounds__(128) void ln_kernel(
    const float* __restrict__ x, const float* __restrict__ gamma,
    const float* __restrict__ beta, int n)
{
    int i = blockIdx.x;
    int t = threadIdx.x;
    int w = t >> 5, l = t & 31;
    float v = x[i * 128 + t];

    float s = v, s2 = v * v;
#pragma unroll
    for (int o = 16; o; o >>= 1) {
        s  += __shfl_xor_sync(0xffffffffu, s, o);
        s2 += __shfl_xor_sync(0xffffffffu, s2, o);
    }
    __shared__ float sa[4], sb[4];
    if (l == 0) { sa[w] = s; sb[w] = s2; }
    __syncthreads();
    s  = sa[0] + sa[1] + sa[2] + sa[3];
    s2 = sb[0] + sb[1] + sb[2] + sb[3];
    __syncthreads();

    float mu  = s * (1.0f / 128.0f);
    float var = s2 * (1.0f / 128.0f) - mu * mu;
    float rstd = rsqrtf(var + 1e-5f);
    float h = (v - mu) * rstd * __ldg(&gamma[t]) + __ldg(&beta[t]);
    h = fmaxf(h, 0.0f);
    g_h[i * 128 + t] = h;

    float q = h * h;
#pragma unroll
    for (int o = 16; o; o >>= 1) q += __shfl_xor_sync(0xffffffffu, q, o);
    if (l == 0) sa[w] = q;
    __syncthreads();
    if (t == 0) g_hnorm[i] = sqrtf(sa[0] + sa[1] + sa[2] + sa[3]);
}

// ---------------------------------------------------------------------------
// Kernel 2: fused SGEMM  g_xlr[n,256] = h @ [W_l | W_r] + [b_l | b_r]
// BM=64, BN=256 (full), BK=32. 256 threads, 8x8 microtile per thread.
// ---------------------------------------------------------------------------
__global__ __launch_bounds__(256) void gemm_kernel(
    const float* __restrict__ Wl, const float* __restrict__ bl,
    const float* __restrict__ Wr, const float* __restrict__ br, int n)
{
    __shared__ float As[64][36];     // padded to kill STS conflicts
    __shared__ float Bs[32][256];

    int tid = threadIdx.x;
    int rowbase = blockIdx.x * 64;
    int rx = tid & 31;   // column group (8 cols)
    int ry = tid >> 5;   // row group (8 rows)

    float acc[8][8];
#pragma unroll
    for (int r = 0; r < 8; r++)
#pragma unroll
        for (int c = 0; c < 8; c++) acc[r][c] = 0.0f;

    for (int kt = 0; kt < 128; kt += 32) {
        // load A tile: 64 rows x 32 k  (512 float4, 2 per thread)
#pragma unroll
        for (int j = 0; j < 2; j++) {
            int idx = tid + j * 256;
            int row = idx >> 3;
            int q = idx & 7;
            float4 v = make_float4(0.f, 0.f, 0.f, 0.f);
            int gr = rowbase + row;
            if (gr < n) v = *(const float4*)&g_h[gr * 128 + kt + q * 4];
            *(float4*)&As[row][q * 4] = v;
        }
        // load B tile: 32 k x 256 cols (2048 float4, 8 per thread)
#pragma unroll
        for (int j = 0; j < 8; j++) {
            int idx = tid + j * 256;
            int krow = idx >> 6;
            int col = (idx & 63) * 4;
            const float* src = (col < 128) ? &Wl[(kt + krow) * 128 + col]
                                           : &Wr[(kt + krow) * 128 + col - 128];
            *(float4*)&Bs[krow][col] = *(const float4*)src;
        }
        __syncthreads();

#pragma unroll
        for (int k = 0; k < 32; k++) {
            float a[8], b[8];
#pragma unroll
            for (int r = 0; r < 8; r++) a[r] = As[ry * 8 + r][k];
            *(float4*)&b[0] = *(float4*)&Bs[k][rx * 8];
            *(float4*)&b[4] = *(float4*)&Bs[k][rx * 8 + 4];
#pragma unroll
            for (int r = 0; r < 8; r++)
#pragma unroll
                for (int c = 0; c < 8; c++) acc[r][c] += a[r] * b[c];
        }
        __syncthreads();
    }

    // epilogue: + bias, store packed
#pragma unroll
    for (int r = 0; r < 8; r++) {
        int gr = rowbase + ry * 8 + r;
        if (gr < n) {
#pragma unroll
            for (int c = 0; c < 8; c += 4) {
                int col = rx * 8 + c;
                const float* bb = (col < 128) ? &bl[col] : &br[col - 128];
                float4 ov;
                ov.x = acc[r][c + 0] + bb[0];
                ov.y = acc[r][c + 1] + bb[1];
                ov.z = acc[r][c + 2] + bb[2];
                ov.w = acc[r][c + 3] + bb[3];
                *(float4*)&g_xlr[gr * 256 + col] = ov;
            }
        }
    }
}

// ---------------------------------------------------------------------------
// CSR build: zero -> histogram(dst) -> exclusive scan -> scatter(src)
// Edges: idx < e are real edges, idx >= e are self loops (src=dst=idx-e).
// edge_index is (2,E) int32 row-major (harness converts int64 -> int32):
// src at ei[idx], dst at ei[e + idx]. Indices clamped defensively.
// ---------------------------------------------------------------------------
__global__ void zero_kernel(int n)
{
    int i = blockIdx.x * blockDim.x + threadIdx.x;
    if (i < n) g_count[i] = 0;
}

__global__ void hist_kernel(const int* __restrict__ ei, int n, int e)
{
    int idx = blockIdx.x * blockDim.x + threadIdx.x;
    int e2 = e + n;
    if (idx >= e2) return;
    int d = (idx < e) ? __ldg(&ei[e + idx]) : (idx - e);
    if ((unsigned)d >= (unsigned)n) d = 0;   // defensive clamp
    atomicAdd(&g_count[d], 1);
}

__global__ __launch_bounds__(1024) void scan_kernel(int n)
{
    __shared__ int sh[1024];
    __shared__ int carry_sh;
    int tid = threadIdx.x;
    if (tid == 0) carry_sh = 0;
    __syncthreads();

    for (int base = 0; base < n; base += 1024) {
        int i = base + tid;
        int v = (i < n) ? g_count[i] : 0;
        sh[tid] = v;
        __syncthreads();
#pragma unroll
        for (int off = 1; off < 1024; off <<= 1) {
            int add = (tid >= off) ? sh[tid - off] : 0;
            __syncthreads();
            sh[tid] += add;
            __syncthreads();
        }
        int excl = sh[tid] - v + carry_sh;
        if (i < n) { g_rowoff[i] = excl; g_cursor[i] = excl; }
        __syncthreads();
        if (tid == 0) carry_sh += sh[1023];
        __syncthreads();
    }
    if (tid == 0) g_rowoff[n] = carry_sh;
}

__global__ void scatter_kernel(const int* __restrict__ ei, int n, int e)
{
    int idx = blockIdx.x * blockDim.x + threadIdx.x;
    int e2 = e + n;
    if (idx >= e2) return;
    int s, d;
    if (idx < e) { s = __ldg(&ei[idx]); d = __ldg(&ei[e + idx]); }
    else         { s = idx - e; d = s; }
    if ((unsigned)s >= (unsigned)n) s = 0;   // defensive clamp
    if ((unsigned)d >= (unsigned)n) d = 0;
    int pos = atomicAdd(&g_cursor[d], 1);
    if (pos < E2MAX) g_csrc[pos] = s;
}

// ---------------------------------------------------------------------------
// Kernel 3: per-node GATv2 with online softmax + MsgNorm + residual.
// One block of 128 threads per node: thread t = (head t/32, channel t%32);
// each warp IS one head, so the per-edge score reduce is a pure warp reduce.
// ---------------------------------------------------------------------------
__global__ __launch_bounds__(128) void gat_kernel(
    const float* __restrict__ x, const float* __restrict__ att,
    const float* __restrict__ bias, const float* __restrict__ scale_p,
    float* __restrict__ out, int n)
{
    int i = blockIdx.x;
    int t = threadIdx.x;
    int w = t >> 5;

    float xr = g_xlr[i * 256 + 128 + t];
    float at = __ldg(&att[t]);
    int beg = g_rowoff[i];
    int end = g_rowoff[i + 1];

    float m = -1e30f, s = 0.0f, acc = 0.0f;
    for (int e = beg; e < end; e++) {
        int j = g_csrc[e];
        float xlv = __ldg(&g_xlr[j * 256 + t]);
        float f = xlv + xr;
        f = (f > 0.0f) ? f : 0.2f * f;        // leaky_relu, slope 0.2
        float p = f * at;
#pragma unroll
        for (int o = 16; o; o >>= 1) p += __shfl_xor_sync(0xffffffffu, p, o);
        // online softmax update (per-head; identical across the warp's lanes)
        float nm  = fmaxf(m, p);
        float sc  = __expf(m - nm);
        float wgt = __expf(p - nm);
        s   = s * sc + wgt;
        acc = acc * sc + wgt * xlv;
        m = nm;
    }

    float o = acc / s + __ldg(&bias[t]);

    // MsgNorm: ||o||_2 over all 128 channels
    float q = o * o;
#pragma unroll
    for (int off = 16; off; off >>= 1) q += __shfl_xor_sync(0xffffffffu, q, off);
    __shared__ float sred[4];
    if ((t & 31) == 0) sred[w] = q;
    __syncthreads();
    float norm = sqrtf(sred[0] + sred[1] + sred[2] + sred[3]);

    float res = o / fmaxf(norm, 1e-12f) * g_hnorm[i] * __ldg(&scale_p[0]);
    out[i * 128 + t] = x[i * 128 + t] + res;
}

// ---------------------------------------------------------------------------
// Launch
// ---------------------------------------------------------------------------
extern "C" void kernel_launch(void* const* d_in, const int* in_sizes, int n_in,
                              void* d_out, int out_size)
{
    const float* x     = (const float*)d_in[0];
    const int*   ei    = (const int*)d_in[1];     // int32 (harness dtype)
    const float* gamma = (const float*)d_in[2];
    const float* beta  = (const float*)d_in[3];
    const float* Wl    = (const float*)d_in[4];
    const float* bl    = (const float*)d_in[5];
    const float* Wr    = (const float*)d_in[6];
    const float* br    = (const float*)d_in[7];
    const float* att   = (const float*)d_in[8];
    const float* bias  = (const float*)d_in[9];
    const float* scale = (const float*)d_in[10];
    float* out = (float*)d_out;

    int n = in_sizes[0] / 128;
    int e = in_sizes[1] / 2;
    int e2 = e + n;

    ln_kernel<<<n, 128>>>(x, gamma, beta, n);
    gemm_kernel<<<(n + 63) / 64, 256>>>(Wl, bl, Wr, br, n);
    zero_kernel<<<(n + 255) / 256, 256>>>(n);
    hist_kernel<<<(e2 + 255) / 256, 256>>>(ei, n, e);
    scan_kernel<<<1, 1024>>>(n);
    scatter_kernel<<<(e2 + 255) / 256, 256>>>(ei, n, e);
    gat_kernel<<<n, 128>>>(x, att, bias, scale, out, n);
}

// round 7
// speedup vs baseline: 1.1471x; 1.1471x over previous
#include <cuda_runtime.h>
#include <cuda_bf16.h>

// Problem constants: N=50000, E=800000, D=128, H=4, C=32
#define NMAX 50048
#define E2MAX 860000

__device__ float g_mu[NMAX];
__device__ float g_rstd[NMAX];
__device__ float g_hnorm[NMAX];
__device__ float g_xlr[NMAX * 256];    // [xl | xr] packed per node
__device__ int   g_count[NMAX];
__device__ int   g_rowoff[NMAX + 1];
__device__ int   g_cursor[NMAX];
__device__ int   g_csrc[E2MAX];
__device__ int   g_bsum[64];

// ---------------------------------------------------------------------------
// Kernel 1: LN stats (mu, rstd) + ||relu(ln(x))||_2 per node. Also zeros g_count.
// ---------------------------------------------------------------------------
__global__ __launch_bounds__(128) void ln_stats_kernel(
    const float* __restrict__ x, const float* __restrict__ gamma,
    const float* __restrict__ beta, int n)
{
    int i = blockIdx.x;
    int t = threadIdx.x;
    int w = t >> 5, l = t & 31;
    float v = x[i * 128 + t];

    float s = v, s2 = v * v;
#pragma unroll
    for (int o = 16; o; o >>= 1) {
        s  += __shfl_xor_sync(0xffffffffu, s, o);
        s2 += __shfl_xor_sync(0xffffffffu, s2, o);
    }
    __shared__ float sa[4], sb[4];
    if (l == 0) { sa[w] = s; sb[w] = s2; }
    __syncthreads();
    s  = sa[0] + sa[1] + sa[2] + sa[3];
    s2 = sb[0] + sb[1] + sb[2] + sb[3];
    __syncthreads();

    float mu  = s * (1.0f / 128.0f);
    float var = s2 * (1.0f / 128.0f) - mu * mu;
    float rstd = rsqrtf(var + 1e-5f);
    float h = fmaxf((v - mu) * rstd * __ldg(&gamma[t]) + __ldg(&beta[t]), 0.0f);

    float q = h * h;
#pragma unroll
    for (int o = 16; o; o >>= 1) q += __shfl_xor_sync(0xffffffffu, q, o);
    if (l == 0) sa[w] = q;
    __syncthreads();
    if (t == 0) {
        g_mu[i] = mu;
        g_rstd[i] = rstd;
        g_hnorm[i] = sqrtf(sa[0] + sa[1] + sa[2] + sa[3]);
        g_count[i] = 0;
    }
}

// ---------------------------------------------------------------------------
// Kernel 2: fused LN+ReLU+SGEMM  g_xlr[n,256] = relu(ln(x)) @ [W_l|W_r] + [b_l|b_r]
// BM=64, BN=256, BK=32. A tile k-major, pad 68 (multiple of 4 -> LDS128 aligned;
// a-fragment loads are warp-broadcast since ry is uniform per warp).
// ---------------------------------------------------------------------------
__global__ __launch_bounds__(256) void gemm_kernel(
    const float* __restrict__ x, const float* __restrict__ gamma,
    const float* __restrict__ beta,
    const float* __restrict__ Wl, const float* __restrict__ bl,
    const float* __restrict__ Wr, const float* __restrict__ br, int n)
{
    __shared__ float As[32][68];   // k-major, pad 68 (16B-aligned rows)
    __shared__ float Bs[32][256];

    int tid = threadIdx.x;
    int rowbase = blockIdx.x * 64;
    int rx = tid & 31;
    int ry = tid >> 5;

    float acc[8][8];
#pragma unroll
    for (int r = 0; r < 8; r++)
#pragma unroll
        for (int c = 0; c < 8; c++) acc[r][c] = 0.0f;

    for (int kt = 0; kt < 128; kt += 32) {
        // A tile: 64 rows x 32 k, with LN+ReLU applied on the fly
#pragma unroll
        for (int j = 0; j < 2; j++) {
            int idx = tid + j * 256;
            int row = idx >> 3;
            int q = idx & 7;
            int gr = rowbase + row;
            float4 hv = make_float4(0.f, 0.f, 0.f, 0.f);
            if (gr < n) {
                float4 v  = *(const float4*)&x[gr * 128 + kt + q * 4];
                float4 gm = *(const float4*)&gamma[kt + q * 4];
                float4 bt = *(const float4*)&beta[kt + q * 4];
                float mu = g_mu[gr], rs = g_rstd[gr];
                hv.x = fmaxf((v.x - mu) * rs * gm.x + bt.x, 0.f);
                hv.y = fmaxf((v.y - mu) * rs * gm.y + bt.y, 0.f);
                hv.z = fmaxf((v.z - mu) * rs * gm.z + bt.z, 0.f);
                hv.w = fmaxf((v.w - mu) * rs * gm.w + bt.w, 0.f);
            }
            As[q * 4 + 0][row] = hv.x;
            As[q * 4 + 1][row] = hv.y;
            As[q * 4 + 2][row] = hv.z;
            As[q * 4 + 3][row] = hv.w;
        }
        // B tile: 32 k x 256 cols
#pragma unroll
        for (int j = 0; j < 8; j++) {
            int idx = tid + j * 256;
            int krow = idx >> 6;
            int col = (idx & 63) * 4;
            const float* src = (col < 128) ? &Wl[(kt + krow) * 128 + col]
                                           : &Wr[(kt + krow) * 128 + col - 128];
            *(float4*)&Bs[krow][col] = *(const float4*)src;
        }
        __syncthreads();

#pragma unroll
        for (int k = 0; k < 32; k++) {
            float a[8], b[8];
            *(float4*)&a[0] = *(float4*)&As[k][ry * 8];       // broadcast, aligned
            *(float4*)&a[4] = *(float4*)&As[k][ry * 8 + 4];
            *(float4*)&b[0] = *(float4*)&Bs[k][rx * 8];
            *(float4*)&b[4] = *(float4*)&Bs[k][rx * 8 + 4];
#pragma unroll
            for (int r = 0; r < 8; r++)
#pragma unroll
                for (int c = 0; c < 8; c++) acc[r][c] += a[r] * b[c];
        }
        __syncthreads();
    }

#pragma unroll
    for (int r = 0; r < 8; r++) {
        int gr = rowbase + ry * 8 + r;
        if (gr < n) {
#pragma unroll
            for (int c = 0; c < 8; c += 4) {
                int col = rx * 8 + c;
                const float* bb = (col < 128) ? &bl[col] : &br[col - 128];
                float4 ov;
                ov.x = acc[r][c + 0] + bb[0];
                ov.y = acc[r][c + 1] + bb[1];
                ov.z = acc[r][c + 2] + bb[2];
                ov.w = acc[r][c + 3] + bb[3];
                *(float4*)&g_xlr[gr * 256 + col] = ov;
            }
        }
    }
}

// ---------------------------------------------------------------------------
// CSR build: hist -> scanA (per-block excl scan) -> scanC (finalize) -> scatter
// ---------------------------------------------------------------------------
__global__ void hist_kernel(const int* __restrict__ ei, int n, int e)
{
    int idx = blockIdx.x * blockDim.x + threadIdx.x;
    int e2 = e + n;
    if (idx >= e2) return;
    int d = (idx < e) ? __ldg(&ei[e + idx]) : (idx - e);
    if ((unsigned)d >= (unsigned)n) d = 0;
    atomicAdd(&g_count[d], 1);
}

__global__ __launch_bounds__(1024) void scanA_kernel(int n)
{
    __shared__ int ws[32];
    int i = blockIdx.x * 1024 + threadIdx.x;
    int t = threadIdx.x;
    int l = t & 31, w = t >> 5;
    int v = (i < n) ? g_count[i] : 0;

    // inclusive warp scan
    int sc = v;
#pragma unroll
    for (int o = 1; o < 32; o <<= 1) {
        int u = __shfl_up_sync(0xffffffffu, sc, o);
        if (l >= o) sc += u;
    }
    if (l == 31) ws[w] = sc;
    __syncthreads();
    if (w == 0) {
        int q = (l < 32) ? ws[l] : 0;
#pragma unroll
        for (int o = 1; o < 32; o <<= 1) {
            int u = __shfl_up_sync(0xffffffffu, q, o);
            if (l >= o) q += u;
        }
        ws[l] = q;
    }
    __syncthreads();
    int excl = sc - v + (w ? ws[w - 1] : 0);
    if (i < n) g_rowoff[i] = excl;            // block-local exclusive scan
    if (t == 1023) g_bsum[blockIdx.x] = excl + v;  // block total
}

__global__ __launch_bounds__(1024) void scanC_kernel(int n, int nblk)
{
    // every block recomputes the block-offset prefix locally (nblk <= 64)
    __shared__ int boff_sh;
    int t = threadIdx.x;
    if (t < 32) {
        int acc = 0;
        for (int b = t; b < blockIdx.x; b += 32) acc += g_bsum[b];
#pragma unroll
        for (int o = 16; o; o >>= 1) acc += __shfl_xor_sync(0xffffffffu, acc, o);
        if (t == 0) boff_sh = acc;
    }
    __syncthreads();
    int boff = boff_sh;
    int i = blockIdx.x * 1024 + t;
    if (i < n) {
        int v = g_rowoff[i] + boff;
        g_rowoff[i] = v;
        g_cursor[i] = v;
    }
    if (blockIdx.x == 0 && t < 32) {
        int tot = 0;
        for (int b = t; b < nblk; b += 32) tot += g_bsum[b];
#pragma unroll
        for (int o = 16; o; o >>= 1) tot += __shfl_xor_sync(0xffffffffu, tot, o);
        if (t == 0) g_rowoff[n] = tot;
    }
}

__global__ void scatter_kernel(const int* __restrict__ ei, int n, int e)
{
    int idx = blockIdx.x * blockDim.x + threadIdx.x;
    int e2 = e + n;
    if (idx >= e2) return;
    int s, d;
    if (idx < e) { s = __ldg(&ei[idx]); d = __ldg(&ei[e + idx]); }
    else         { s = idx - e; d = s; }
    if ((unsigned)s >= (unsigned)n) s = 0;
    if ((unsigned)d >= (unsigned)n) d = 0;
    int pos = atomicAdd(&g_cursor[d], 1);
    if (pos < E2MAX) g_csrc[pos] = s;
}

// ---------------------------------------------------------------------------
// Kernel 3: per-node GATv2, online softmax, edge loop unrolled x4 for ILP.
// ---------------------------------------------------------------------------
__device__ __forceinline__ void online_upd(float& m, float& s, float& acc,
                                           float p, float v)
{
    float nm  = fmaxf(m, p);
    float sc  = __expf(m - nm);
    float wgt = __expf(p - nm);
    s   = s * sc + wgt;
    acc = acc * sc + wgt * v;
    m = nm;
}

__global__ __launch_bounds__(128) void gat_kernel(
    const float* __restrict__ x, const float* __restrict__ att,
    const float* __restrict__ bias, const float* __restrict__ scale_p,
    float* __restrict__ out, int n)
{
    int i = blockIdx.x;
    int t = threadIdx.x;
    int w = t >> 5;

    float xr = g_xlr[i * 256 + 128 + t];
    float at = __ldg(&att[t]);
    int beg = g_rowoff[i];
    int end = g_rowoff[i + 1];

    float m = -1e30f, s = 0.0f, acc = 0.0f;
    int e = beg;
    for (; e + 4 <= end; e += 4) {
        int j0 = g_csrc[e + 0], j1 = g_csrc[e + 1];
        int j2 = g_csrc[e + 2], j3 = g_csrc[e + 3];
        float v0 = __ldg(&g_xlr[j0 * 256 + t]);
        float v1 = __ldg(&g_xlr[j1 * 256 + t]);
        float v2 = __ldg(&g_xlr[j2 * 256 + t]);
        float v3 = __ldg(&g_xlr[j3 * 256 + t]);
        float f0 = v0 + xr, f1 = v1 + xr, f2 = v2 + xr, f3 = v3 + xr;
        float p0 = ((f0 > 0.f) ? f0 : 0.2f * f0) * at;
        float p1 = ((f1 > 0.f) ? f1 : 0.2f * f1) * at;
        float p2 = ((f2 > 0.f) ? f2 : 0.2f * f2) * at;
        float p3 = ((f3 > 0.f) ? f3 : 0.2f * f3) * at;
#pragma unroll
        for (int o = 16; o; o >>= 1) {
            p0 += __shfl_xor_sync(0xffffffffu, p0, o);
            p1 += __shfl_xor_sync(0xffffffffu, p1, o);
            p2 += __shfl_xor_sync(0xffffffffu, p2, o);
            p3 += __shfl_xor_sync(0xffffffffu, p3, o);
        }
        online_upd(m, s, acc, p0, v0);
        online_upd(m, s, acc, p1, v1);
        online_upd(m, s, acc, p2, v2);
        online_upd(m, s, acc, p3, v3);
    }
    for (; e < end; e++) {
        int j = g_csrc[e];
        float v = __ldg(&g_xlr[j * 256 + t]);
        float f = v + xr;
        float p = ((f > 0.f) ? f : 0.2f * f) * at;
#pragma unroll
        for (int o = 16; o; o >>= 1) p += __shfl_xor_sync(0xffffffffu, p, o);
        online_upd(m, s, acc, p, v);
    }

    float o = acc / s + __ldg(&bias[t]);

    float q = o * o;
#pragma unroll
    for (int off = 16; off; off >>= 1) q += __shfl_xor_sync(0xffffffffu, q, off);
    __shared__ float sred[4];
    if ((t & 31) == 0) sred[w] = q;
    __syncthreads();
    float norm = sqrtf(sred[0] + sred[1] + sred[2] + sred[3]);

    float res = o / fmaxf(norm, 1e-12f) * g_hnorm[i] * __ldg(&scale_p[0]);
    out[i * 128 + t] = x[i * 128 + t] + res;
}

// ---------------------------------------------------------------------------
extern "C" void kernel_launch(void* const* d_in, const int* in_sizes, int n_in,
                              void* d_out, int out_size)
{
    const float* x     = (const float*)d_in[0];
    const int*   ei    = (const int*)d_in[1];
    const float* gamma = (const float*)d_in[2];
    const float* beta  = (const float*)d_in[3];
    const float* Wl    = (const float*)d_in[4];
    const float* bl    = (const float*)d_in[5];
    const float* Wr    = (const float*)d_in[6];
    const float* br    = (const float*)d_in[7];
    const float* att   = (const float*)d_in[8];
    const float* bias  = (const float*)d_in[9];
    const float* scale = (const float*)d_in[10];
    float* out = (float*)d_out;

    int n = in_sizes[0] / 128;
    int e = in_sizes[1] / 2;
    int e2 = e + n;
    int nblk = (n + 1023) / 1024;

    ln_stats_kernel<<<n, 128>>>(x, gamma, beta, n);
    gemm_kernel<<<(n + 63) / 64, 256>>>(x, gamma, beta, Wl, bl, Wr, br, n);
    hist_kernel<<<(e2 + 255) / 256, 256>>>(ei, n, e);
    scanA_kernel<<<nblk, 1024>>>(n);
    scanC_kernel<<<nblk, 1024>>>(n, nblk);
    scatter_kernel<<<(e2 + 255) / 256, 256>>>(ei, n, e);
    gat_kernel<<<n, 128>>>(x, att, bias, scale, out, n);
}

// round 8
// speedup vs baseline: 1.3109x; 1.1428x over previous
#include <cuda_runtime.h>
#include <cuda_bf16.h>

// Problem constants: N=50000, E=800000, D=128, H=4, C=32
#define NMAX 50048
#define E2MAX 860000

__device__ float g_mu[NMAX];
__device__ float g_rstd[NMAX];
__device__ float g_hnorm[NMAX];
__device__ float g_xlr[NMAX * 256];    // [xl | xr] packed per node
__device__ int   g_count[NMAX];
__device__ int   g_rowoff[NMAX + 1];
__device__ int   g_cursor[NMAX];
__device__ int   g_csrc[E2MAX];
__device__ int   g_bsum[64];

// ---------------------------------------------------------------------------
// Kernel 1: LN stats (mu, rstd) + ||relu(ln(x))||_2 per node. Also zeros g_count.
// ---------------------------------------------------------------------------
__global__ __launch_bounds__(128) void ln_stats_kernel(
    const float* __restrict__ x, const float* __restrict__ gamma,
    const float* __restrict__ beta, int n)
{
    int i = blockIdx.x;
    int t = threadIdx.x;
    int w = t >> 5, l = t & 31;
    float v = x[i * 128 + t];

    float s = v, s2 = v * v;
#pragma unroll
    for (int o = 16; o; o >>= 1) {
        s  += __shfl_xor_sync(0xffffffffu, s, o);
        s2 += __shfl_xor_sync(0xffffffffu, s2, o);
    }
    __shared__ float sa[4], sb[4];
    if (l == 0) { sa[w] = s; sb[w] = s2; }
    __syncthreads();
    s  = sa[0] + sa[1] + sa[2] + sa[3];
    s2 = sb[0] + sb[1] + sb[2] + sb[3];
    __syncthreads();

    float mu  = s * (1.0f / 128.0f);
    float var = s2 * (1.0f / 128.0f) - mu * mu;
    float rstd = rsqrtf(var + 1e-5f);
    float h = fmaxf((v - mu) * rstd * __ldg(&gamma[t]) + __ldg(&beta[t]), 0.0f);

    float q = h * h;
#pragma unroll
    for (int o = 16; o; o >>= 1) q += __shfl_xor_sync(0xffffffffu, q, o);
    if (l == 0) sa[w] = q;
    __syncthreads();
    if (t == 0) {
        g_mu[i] = mu;
        g_rstd[i] = rstd;
        g_hnorm[i] = sqrtf(sa[0] + sa[1] + sa[2] + sa[3]);
        g_count[i] = 0;
    }
}

// ---------------------------------------------------------------------------
// Kernel 2: fused LN+ReLU+SGEMM  g_xlr[n,256] = relu(ln(x)) @ [W_l|W_r] + [b_l|b_r]
// BM=64, BN=256, BK=32. A tile k-major, pad 68 (16B-aligned rows, broadcast reads).
// ---------------------------------------------------------------------------
__global__ __launch_bounds__(256) void gemm_kernel(
    const float* __restrict__ x, const float* __restrict__ gamma,
    const float* __restrict__ beta,
    const float* __restrict__ Wl, const float* __restrict__ bl,
    const float* __restrict__ Wr, const float* __restrict__ br, int n)
{
    __shared__ float As[32][68];
    __shared__ float Bs[32][256];

    int tid = threadIdx.x;
    int rowbase = blockIdx.x * 64;
    int rx = tid & 31;
    int ry = tid >> 5;

    float acc[8][8];
#pragma unroll
    for (int r = 0; r < 8; r++)
#pragma unroll
        for (int c = 0; c < 8; c++) acc[r][c] = 0.0f;

    for (int kt = 0; kt < 128; kt += 32) {
#pragma unroll
        for (int j = 0; j < 2; j++) {
            int idx = tid + j * 256;
            int row = idx >> 3;
            int q = idx & 7;
            int gr = rowbase + row;
            float4 hv = make_float4(0.f, 0.f, 0.f, 0.f);
            if (gr < n) {
                float4 v  = *(const float4*)&x[gr * 128 + kt + q * 4];
                float4 gm = *(const float4*)&gamma[kt + q * 4];
                float4 bt = *(const float4*)&beta[kt + q * 4];
                float mu = g_mu[gr], rs = g_rstd[gr];
                hv.x = fmaxf((v.x - mu) * rs * gm.x + bt.x, 0.f);
                hv.y = fmaxf((v.y - mu) * rs * gm.y + bt.y, 0.f);
                hv.z = fmaxf((v.z - mu) * rs * gm.z + bt.z, 0.f);
                hv.w = fmaxf((v.w - mu) * rs * gm.w + bt.w, 0.f);
            }
            As[q * 4 + 0][row] = hv.x;
            As[q * 4 + 1][row] = hv.y;
            As[q * 4 + 2][row] = hv.z;
            As[q * 4 + 3][row] = hv.w;
        }
#pragma unroll
        for (int j = 0; j < 8; j++) {
            int idx = tid + j * 256;
            int krow = idx >> 6;
            int col = (idx & 63) * 4;
            const float* src = (col < 128) ? &Wl[(kt + krow) * 128 + col]
                                           : &Wr[(kt + krow) * 128 + col - 128];
            *(float4*)&Bs[krow][col] = *(const float4*)src;
        }
        __syncthreads();

#pragma unroll
        for (int k = 0; k < 32; k++) {
            float a[8], b[8];
            *(float4*)&a[0] = *(float4*)&As[k][ry * 8];
            *(float4*)&a[4] = *(float4*)&As[k][ry * 8 + 4];
            *(float4*)&b[0] = *(float4*)&Bs[k][rx * 8];
            *(float4*)&b[4] = *(float4*)&Bs[k][rx * 8 + 4];
#pragma unroll
            for (int r = 0; r < 8; r++)
#pragma unroll
                for (int c = 0; c < 8; c++) acc[r][c] += a[r] * b[c];
        }
        __syncthreads();
    }

#pragma unroll
    for (int r = 0; r < 8; r++) {
        int gr = rowbase + ry * 8 + r;
        if (gr < n) {
#pragma unroll
            for (int c = 0; c < 8; c += 4) {
                int col = rx * 8 + c;
                const float* bb = (col < 128) ? &bl[col] : &br[col - 128];
                float4 ov;
                ov.x = acc[r][c + 0] + bb[0];
                ov.y = acc[r][c + 1] + bb[1];
                ov.z = acc[r][c + 2] + bb[2];
                ov.w = acc[r][c + 3] + bb[3];
                *(float4*)&g_xlr[gr * 256 + col] = ov;
            }
        }
    }
}

// ---------------------------------------------------------------------------
// CSR build: hist -> scanA -> scanC -> scatter
// ---------------------------------------------------------------------------
__global__ void hist_kernel(const int* __restrict__ ei, int n, int e)
{
    int idx = blockIdx.x * blockDim.x + threadIdx.x;
    int e2 = e + n;
    if (idx >= e2) return;
    int d = (idx < e) ? __ldg(&ei[e + idx]) : (idx - e);
    if ((unsigned)d >= (unsigned)n) d = 0;
    atomicAdd(&g_count[d], 1);
}

__global__ __launch_bounds__(1024) void scanA_kernel(int n)
{
    __shared__ int ws[32];
    int i = blockIdx.x * 1024 + threadIdx.x;
    int t = threadIdx.x;
    int l = t & 31, w = t >> 5;
    int v = (i < n) ? g_count[i] : 0;

    int sc = v;
#pragma unroll
    for (int o = 1; o < 32; o <<= 1) {
        int u = __shfl_up_sync(0xffffffffu, sc, o);
        if (l >= o) sc += u;
    }
    if (l == 31) ws[w] = sc;
    __syncthreads();
    if (w == 0) {
        int q = (l < 32) ? ws[l] : 0;
#pragma unroll
        for (int o = 1; o < 32; o <<= 1) {
            int u = __shfl_up_sync(0xffffffffu, q, o);
            if (l >= o) q += u;
        }
        ws[l] = q;
    }
    __syncthreads();
    int excl = sc - v + (w ? ws[w - 1] : 0);
    if (i < n) g_rowoff[i] = excl;
    if (t == 1023) g_bsum[blockIdx.x] = excl + v;
}

__global__ __launch_bounds__(1024) void scanC_kernel(int n, int nblk)
{
    __shared__ int boff_sh;
    int t = threadIdx.x;
    if (t < 32) {
        int acc = 0;
        for (int b = t; b < blockIdx.x; b += 32) acc += g_bsum[b];
#pragma unroll
        for (int o = 16; o; o >>= 1) acc += __shfl_xor_sync(0xffffffffu, acc, o);
        if (t == 0) boff_sh = acc;
    }
    __syncthreads();
    int boff = boff_sh;
    int i = blockIdx.x * 1024 + t;
    if (i < n) {
        int v = g_rowoff[i] + boff;
        g_rowoff[i] = v;
        g_cursor[i] = v;
    }
    if (blockIdx.x == 0 && t < 32) {
        int tot = 0;
        for (int b = t; b < nblk; b += 32) tot += g_bsum[b];
#pragma unroll
        for (int o = 16; o; o >>= 1) tot += __shfl_xor_sync(0xffffffffu, tot, o);
        if (t == 0) g_rowoff[n] = tot;
    }
}

__global__ void scatter_kernel(const int* __restrict__ ei, int n, int e)
{
    int idx = blockIdx.x * blockDim.x + threadIdx.x;
    int e2 = e + n;
    if (idx >= e2) return;
    int s, d;
    if (idx < e) { s = __ldg(&ei[idx]); d = __ldg(&ei[e + idx]); }
    else         { s = idx - e; d = s; }
    if ((unsigned)s >= (unsigned)n) s = 0;
    if ((unsigned)d >= (unsigned)n) d = 0;
    int pos = atomicAdd(&g_cursor[d], 1);
    if (pos < E2MAX) g_csrc[pos] = s;
}

// ---------------------------------------------------------------------------
// Kernel 3: per-node GATv2. Warp = head. Lane = (edge-group g = l>>3, quad q = l&7).
// 4 edges per warp-iteration: float4 gather per lane, 8-lane dot reduce (3 SHFL),
// single online-softmax update covering all 4 edges (2 SHFL max + 2 SHFL sum + 2 exp).
// ---------------------------------------------------------------------------
__global__ __launch_bounds__(128) void gat_kernel(
    const float* __restrict__ x, const float* __restrict__ att,
    const float* __restrict__ bias, const float* __restrict__ scale_p,
    float* __restrict__ out, int n)
{
    int i = blockIdx.x;
    int t = threadIdx.x;
    int w = t >> 5;        // head
    int l = t & 31;
    int g = l >> 3;        // edge subgroup 0..3
    int q = l & 7;         // channel quad 0..7
    int cbase = w * 32 + q * 4;

    float4 xr4 = *(const float4*)&g_xlr[i * 256 + 128 + cbase];
    float4 at4 = *(const float4*)&att[cbase];
    int beg = g_rowoff[i];
    int end = g_rowoff[i + 1];

    float m = -1e30f, s = 0.0f;
    float4 acc = make_float4(0.f, 0.f, 0.f, 0.f);

    for (int e = beg; e < end; e += 4) {
        int ee = e + g;
        bool valid = ee < end;
        int j = g_csrc[valid ? ee : beg];
        float4 v = *(const float4*)&g_xlr[j * 256 + cbase];

        float z0 = v.x + xr4.x, z1 = v.y + xr4.y;
        float z2 = v.z + xr4.z, z3 = v.w + xr4.w;
        // leaky_relu slope 0.2: max(z, 0.2z)
        float p;
        p = at4.x * fmaxf(z0, 0.2f * z0);
        p = fmaf(at4.y, fmaxf(z1, 0.2f * z1), p);
        p = fmaf(at4.z, fmaxf(z2, 0.2f * z2), p);
        p = fmaf(at4.w, fmaxf(z3, 0.2f * z3), p);
        // dot over the 8 quads of this edge subgroup
        p += __shfl_xor_sync(0xffffffffu, p, 1);
        p += __shfl_xor_sync(0xffffffffu, p, 2);
        p += __shfl_xor_sync(0xffffffffu, p, 4);
        if (!valid) p = -1e30f;

        // max over the 4 edge subgroups
        float pm = p;
        pm = fmaxf(pm, __shfl_xor_sync(0xffffffffu, pm, 8));
        pm = fmaxf(pm, __shfl_xor_sync(0xffffffffu, pm, 16));
        float nm = fmaxf(m, pm);
        float sc  = __expf(m - nm);
        float wgt = __expf(p - nm);           // 0 for invalid lanes
        float ws = wgt;
        ws += __shfl_xor_sync(0xffffffffu, ws, 8);
        ws += __shfl_xor_sync(0xffffffffu, ws, 16);
        s = s * sc + ws;
        m = nm;
        acc.x = acc.x * sc + wgt * v.x;
        acc.y = acc.y * sc + wgt * v.y;
        acc.z = acc.z * sc + wgt * v.z;
        acc.w = acc.w * sc + wgt * v.w;
    }

    // sum accumulator across the 4 edge subgroups (same q -> same channels)
    acc.x += __shfl_xor_sync(0xffffffffu, acc.x, 8);
    acc.y += __shfl_xor_sync(0xffffffffu, acc.y, 8);
    acc.z += __shfl_xor_sync(0xffffffffu, acc.z, 8);
    acc.w += __shfl_xor_sync(0xffffffffu, acc.w, 8);
    acc.x += __shfl_xor_sync(0xffffffffu, acc.x, 16);
    acc.y += __shfl_xor_sync(0xffffffffu, acc.y, 16);
    acc.z += __shfl_xor_sync(0xffffffffu, acc.z, 16);
    acc.w += __shfl_xor_sync(0xffffffffu, acc.w, 16);

    float inv_s = 1.0f / s;
    float4 b4 = *(const float4*)&bias[cbase];
    float o0 = acc.x * inv_s + b4.x;
    float o1 = acc.y * inv_s + b4.y;
    float o2 = acc.z * inv_s + b4.z;
    float o3 = acc.w * inv_s + b4.w;

    // MsgNorm: sum of squares over all 128 channels.
    // Per-lane quad sum; reduce over q (offsets 1,2,4) -> per-head sum (dup x4 groups is
    // avoided because the reduce is only over the q dimension).
    float qq = o0 * o0 + o1 * o1 + o2 * o2 + o3 * o3;
    qq += __shfl_xor_sync(0xffffffffu, qq, 1);
    qq += __shfl_xor_sync(0xffffffffu, qq, 2);
    qq += __shfl_xor_sync(0xffffffffu, qq, 4);
    __shared__ float sred[4];
    if (l == 0) sred[w] = qq;
    __syncthreads();
    float norm = sqrtf(sred[0] + sred[1] + sred[2] + sred[3]);

    float k = g_hnorm[i] * __ldg(&scale_p[0]) / fmaxf(norm, 1e-12f);
    if (g == 0) {
        const float4 xv = *(const float4*)&x[i * 128 + cbase];
        float4 ov;
        ov.x = xv.x + o0 * k;
        ov.y = xv.y + o1 * k;
        ov.z = xv.z + o2 * k;
        ov.w = xv.w + o3 * k;
        *(float4*)&out[i * 128 + cbase] = ov;
    }
}

// ---------------------------------------------------------------------------
extern "C" void kernel_launch(void* const* d_in, const int* in_sizes, int n_in,
                              void* d_out, int out_size)
{
    const float* x     = (const float*)d_in[0];
    const int*   ei    = (const int*)d_in[1];
    const float* gamma = (const float*)d_in[2];
    const float* beta  = (const float*)d_in[3];
    const float* Wl    = (const float*)d_in[4];
    const float* bl    = (const float*)d_in[5];
    const float* Wr    = (const float*)d_in[6];
    const float* br    = (const float*)d_in[7];
    const float* att   = (const float*)d_in[8];
    const float* bias  = (const float*)d_in[9];
    const float* scale = (const float*)d_in[10];
    float* out = (float*)d_out;

    int n = in_sizes[0] / 128;
    int e = in_sizes[1] / 2;
    int e2 = e + n;
    int nblk = (n + 1023) / 1024;

    ln_stats_kernel<<<n, 128>>>(x, gamma, beta, n);
    gemm_kernel<<<(n + 63) / 64, 256>>>(x, gamma, beta, Wl, bl, Wr, br, n);
    hist_kernel<<<(e2 + 255) / 256, 256>>>(ei, n, e);
    scanA_kernel<<<nblk, 1024>>>(n);
    scanC_kernel<<<nblk, 1024>>>(n, nblk);
    scatter_kernel<<<(e2 + 255) / 256, 256>>>(ei, n, e);
    gat_kernel<<<n, 128>>>(x, att, bias, scale, out, n);
}

// round 10
// speedup vs baseline: 1.4182x; 1.0818x over previous
#include <cuda_runtime.h>
#include <cuda_bf16.h>

// Problem constants: N=50000, E=800000, D=128, H=4, C=32
#define NMAX 50048
#define E2MAX 860000

__device__ float g_mu[NMAX];
__device__ float g_rstd[NMAX];
__device__ float g_hnorm[NMAX];
__device__ float g_xlr[NMAX * 256];    // [xl | xr] packed per node
__device__ int   g_count[NMAX];
__device__ int   g_rowoff[NMAX + 1];
__device__ int   g_cursor[NMAX];
__device__ int   g_csrc[E2MAX];
__device__ int   g_bsum[64];

// packed fp32x2 FMA (B300: 2 MACs/instr; exact IEEE fp32)
__device__ __forceinline__ void fma_f32x2(unsigned long long& d,
                                          unsigned long long a,
                                          unsigned long long b)
{
    asm("fma.rn.f32x2 %0, %1, %2, %0;" : "+l"(d) : "l"(a), "l"(b));
}

union U64F2 { unsigned long long u; float2 f; };

// ---------------------------------------------------------------------------
// Kernel 1: LN stats (mu, rstd) + ||relu(ln(x))||_2 per node. Also zeros g_count.
// ---------------------------------------------------------------------------
__global__ __launch_bounds__(128) void ln_stats_kernel(
    const float* __restrict__ x, const float* __restrict__ gamma,
    const float* __restrict__ beta, int n)
{
    int i = blockIdx.x;
    int t = threadIdx.x;
    int w = t >> 5, l = t & 31;
    float v = x[i * 128 + t];

    float s = v, s2 = v * v;
#pragma unroll
    for (int o = 16; o; o >>= 1) {
        s  += __shfl_xor_sync(0xffffffffu, s, o);
        s2 += __shfl_xor_sync(0xffffffffu, s2, o);
    }
    __shared__ float sa[4], sb[4];
    if (l == 0) { sa[w] = s; sb[w] = s2; }
    __syncthreads();
    s  = sa[0] + sa[1] + sa[2] + sa[3];
    s2 = sb[0] + sb[1] + sb[2] + sb[3];
    __syncthreads();

    float mu  = s * (1.0f / 128.0f);
    float var = s2 * (1.0f / 128.0f) - mu * mu;
    float rstd = rsqrtf(var + 1e-5f);
    float h = fmaxf((v - mu) * rstd * __ldg(&gamma[t]) + __ldg(&beta[t]), 0.0f);

    float q = h * h;
#pragma unroll
    for (int o = 16; o; o >>= 1) q += __shfl_xor_sync(0xffffffffu, q, o);
    if (l == 0) sa[w] = q;
    __syncthreads();
    if (t == 0) {
        g_mu[i] = mu;
        g_rstd[i] = rstd;
        g_hnorm[i] = sqrtf(sa[0] + sa[1] + sa[2] + sa[3]);
        g_count[i] = 0;
    }
}

// ---------------------------------------------------------------------------
// Kernel 2: fused LN+ReLU+SGEMM via packed f32x2 FMA.
// BM=64, BN=256, BK=32. A k-major pad 68 (R7-validated layout, broadcast LDS128);
// the (a,a) packed operand is built in registers (MOV on alu pipe, fma pipe
// stays saturated). Smem: 8.7KB + 32.8KB = 41.5KB < 48KB static limit.
// ---------------------------------------------------------------------------
__global__ __launch_bounds__(256) void gemm_kernel(
    const float* __restrict__ x, const float* __restrict__ gamma,
    const float* __restrict__ beta,
    const float* __restrict__ Wl, const float* __restrict__ bl,
    const float* __restrict__ Wr, const float* __restrict__ br, int n)
{
    __shared__ float As[32][68];
    __shared__ float Bs[32][256];

    int tid = threadIdx.x;
    int rowbase = blockIdx.x * 64;
    int rx = tid & 31;
    int ry = tid >> 5;

    unsigned long long acc[8][4];
#pragma unroll
    for (int r = 0; r < 8; r++)
#pragma unroll
        for (int c = 0; c < 4; c++) acc[r][c] = 0ull;

    for (int kt = 0; kt < 128; kt += 32) {
        // A tile: 64 rows x 32 k, LN+ReLU on the fly, k-major
#pragma unroll
        for (int j = 0; j < 2; j++) {
            int idx = tid + j * 256;
            int row = idx >> 3;
            int q = idx & 7;
            int gr = rowbase + row;
            float4 hv = make_float4(0.f, 0.f, 0.f, 0.f);
            if (gr < n) {
                float4 v  = *(const float4*)&x[gr * 128 + kt + q * 4];
                float4 gm = *(const float4*)&gamma[kt + q * 4];
                float4 bt = *(const float4*)&beta[kt + q * 4];
                float mu = g_mu[gr], rs = g_rstd[gr];
                hv.x = fmaxf((v.x - mu) * rs * gm.x + bt.x, 0.f);
                hv.y = fmaxf((v.y - mu) * rs * gm.y + bt.y, 0.f);
                hv.z = fmaxf((v.z - mu) * rs * gm.z + bt.z, 0.f);
                hv.w = fmaxf((v.w - mu) * rs * gm.w + bt.w, 0.f);
            }
            As[q * 4 + 0][row] = hv.x;
            As[q * 4 + 1][row] = hv.y;
            As[q * 4 + 2][row] = hv.z;
            As[q * 4 + 3][row] = hv.w;
        }
        // B tile: 32 k x 256 cols
#pragma unroll
        for (int j = 0; j < 8; j++) {
            int idx = tid + j * 256;
            int krow = idx >> 6;
            int col = (idx & 63) * 4;
            const float* src = (col < 128) ? &Wl[(kt + krow) * 128 + col]
                                           : &Wr[(kt + krow) * 128 + col - 128];
            *(float4*)&Bs[krow][col] = *(const float4*)src;
        }
        __syncthreads();

#pragma unroll
        for (int k = 0; k < 32; k++) {
            float a[8];
            *(float4*)&a[0] = *(float4*)&As[k][ry * 8];       // broadcast, aligned
            *(float4*)&a[4] = *(float4*)&As[k][ry * 8 + 4];
            ulonglong2 bq0 = *(const ulonglong2*)&Bs[k][rx * 8];
            ulonglong2 bq1 = *(const ulonglong2*)&Bs[k][rx * 8 + 4];
#pragma unroll
            for (int r = 0; r < 8; r++) {
                U64F2 ap;
                ap.f = make_float2(a[r], a[r]);               // reg-built (a,a)
                fma_f32x2(acc[r][0], ap.u, bq0.x);
                fma_f32x2(acc[r][1], ap.u, bq0.y);
                fma_f32x2(acc[r][2], ap.u, bq1.x);
                fma_f32x2(acc[r][3], ap.u, bq1.y);
            }
        }
        __syncthreads();
    }

#pragma unroll
    for (int r = 0; r < 8; r++) {
        int gr = rowbase + ry * 8 + r;
        if (gr < n) {
#pragma unroll
            for (int c = 0; c < 8; c += 4) {
                int col = rx * 8 + c;
                const float* bb = (col < 128) ? &bl[col] : &br[col - 128];
                U64F2 p0, p1;
                p0.u = acc[r][c / 2];
                p1.u = acc[r][c / 2 + 1];
                float4 ov;
                ov.x = p0.f.x + bb[0];
                ov.y = p0.f.y + bb[1];
                ov.z = p1.f.x + bb[2];
                ov.w = p1.f.y + bb[3];
                *(float4*)&g_xlr[gr * 256 + col] = ov;
            }
        }
    }
}

// ---------------------------------------------------------------------------
// CSR build: hist -> scanA -> scanC -> scatter
// ---------------------------------------------------------------------------
__global__ void hist_kernel(const int* __restrict__ ei, int n, int e)
{
    int idx = blockIdx.x * blockDim.x + threadIdx.x;
    int e2 = e + n;
    if (idx >= e2) return;
    int d = (idx < e) ? __ldg(&ei[e + idx]) : (idx - e);
    if ((unsigned)d >= (unsigned)n) d = 0;
    atomicAdd(&g_count[d], 1);
}

__global__ __launch_bounds__(1024) void scanA_kernel(int n)
{
    __shared__ int ws[32];
    int i = blockIdx.x * 1024 + threadIdx.x;
    int t = threadIdx.x;
    int l = t & 31, w = t >> 5;
    int v = (i < n) ? g_count[i] : 0;

    int sc = v;
#pragma unroll
    for (int o = 1; o < 32; o <<= 1) {
        int u = __shfl_up_sync(0xffffffffu, sc, o);
        if (l >= o) sc += u;
    }
    if (l == 31) ws[w] = sc;
    __syncthreads();
    if (w == 0) {
        int q = (l < 32) ? ws[l] : 0;
#pragma unroll
        for (int o = 1; o < 32; o <<= 1) {
            int u = __shfl_up_sync(0xffffffffu, q, o);
            if (l >= o) q += u;
        }
        ws[l] = q;
    }
    __syncthreads();
    int excl = sc - v + (w ? ws[w - 1] : 0);
    if (i < n) g_rowoff[i] = excl;
    if (t == 1023) g_bsum[blockIdx.x] = excl + v;
}

__global__ __launch_bounds__(1024) void scanC_kernel(int n, int nblk)
{
    __shared__ int boff_sh;
    int t = threadIdx.x;
    if (t < 32) {
        int acc = 0;
        for (int b = t; b < blockIdx.x; b += 32) acc += g_bsum[b];
#pragma unroll
        for (int o = 16; o; o >>= 1) acc += __shfl_xor_sync(0xffffffffu, acc, o);
        if (t == 0) boff_sh = acc;
    }
    __syncthreads();
    int boff = boff_sh;
    int i = blockIdx.x * 1024 + t;
    if (i < n) {
        int v = g_rowoff[i] + boff;
        g_rowoff[i] = v;
        g_cursor[i] = v;
    }
    if (blockIdx.x == 0 && t < 32) {
        int tot = 0;
        for (int b = t; b < nblk; b += 32) tot += g_bsum[b];
#pragma unroll
        for (int o = 16; o; o >>= 1) tot += __shfl_xor_sync(0xffffffffu, tot, o);
        if (t == 0) g_rowoff[n] = tot;
    }
}

__global__ void scatter_kernel(const int* __restrict__ ei, int n, int e)
{
    int idx = blockIdx.x * blockDim.x + threadIdx.x;
    int e2 = e + n;
    if (idx >= e2) return;
    int s, d;
    if (idx < e) { s = __ldg(&ei[idx]); d = __ldg(&ei[e + idx]); }
    else         { s = idx - e; d = s; }
    if ((unsigned)s >= (unsigned)n) s = 0;
    if ((unsigned)d >= (unsigned)n) d = 0;
    int pos = atomicAdd(&g_cursor[d], 1);
    if (pos < E2MAX) g_csrc[pos] = s;
}

// ---------------------------------------------------------------------------
// Kernel 3: per-node GATv2 WITHOUT online max (|score| << 88 -> exp exact in
// fp32; softmax without max-subtraction identical). Warp = head, lane =
// (edge-group g=l>>3, quad q=l&7). Per 4 edges: 1 gather + 3 SHFL + 1 exp.
// ---------------------------------------------------------------------------
__global__ __launch_bounds__(128) void gat_kernel(
    const float* __restrict__ x, const float* __restrict__ att,
    const float* __restrict__ bias, const float* __restrict__ scale_p,
    float* __restrict__ out, int n)
{
    int i = blockIdx.x;
    int t = threadIdx.x;
    int w = t >> 5;        // head
    int l = t & 31;
    int g = l >> 3;        // edge subgroup 0..3
    int q = l & 7;         // channel quad 0..7
    int cbase = w * 32 + q * 4;

    float4 xr4 = *(const float4*)&g_xlr[i * 256 + 128 + cbase];
    float4 at4 = *(const float4*)&att[cbase];
    int beg = g_rowoff[i];
    int end = g_rowoff[i + 1];

    float s = 0.0f;
    float4 acc = make_float4(0.f, 0.f, 0.f, 0.f);

    for (int e = beg; e < end; e += 4) {
        int ee = e + g;
        bool valid = ee < end;
        int j = g_csrc[valid ? ee : beg];
        float4 v = *(const float4*)&g_xlr[j * 256 + cbase];

        float z0 = v.x + xr4.x, z1 = v.y + xr4.y;
        float z2 = v.z + xr4.z, z3 = v.w + xr4.w;
        float p;
        p = at4.x * fmaxf(z0, 0.2f * z0);
        p = fmaf(at4.y, fmaxf(z1, 0.2f * z1), p);
        p = fmaf(at4.z, fmaxf(z2, 0.2f * z2), p);
        p = fmaf(at4.w, fmaxf(z3, 0.2f * z3), p);
        p += __shfl_xor_sync(0xffffffffu, p, 1);
        p += __shfl_xor_sync(0xffffffffu, p, 2);
        p += __shfl_xor_sync(0xffffffffu, p, 4);

        float wgt = valid ? __expf(p) : 0.0f;
        s += wgt;
        acc.x = fmaf(wgt, v.x, acc.x);
        acc.y = fmaf(wgt, v.y, acc.y);
        acc.z = fmaf(wgt, v.z, acc.z);
        acc.w = fmaf(wgt, v.w, acc.w);
    }

#pragma unroll
    for (int o = 8; o <= 16; o <<= 1) {
        s     += __shfl_xor_sync(0xffffffffu, s, o);
        acc.x += __shfl_xor_sync(0xffffffffu, acc.x, o);
        acc.y += __shfl_xor_sync(0xffffffffu, acc.y, o);
        acc.z += __shfl_xor_sync(0xffffffffu, acc.z, o);
        acc.w += __shfl_xor_sync(0xffffffffu, acc.w, o);
    }

    float inv_s = 1.0f / s;
    float4 b4 = *(const float4*)&bias[cbase];
    float o0 = acc.x * inv_s + b4.x;
    float o1 = acc.y * inv_s + b4.y;
    float o2 = acc.z * inv_s + b4.z;
    float o3 = acc.w * inv_s + b4.w;

    float qq = o0 * o0 + o1 * o1 + o2 * o2 + o3 * o3;
    qq += __shfl_xor_sync(0xffffffffu, qq, 1);
    qq += __shfl_xor_sync(0xffffffffu, qq, 2);
    qq += __shfl_xor_sync(0xffffffffu, qq, 4);
    __shared__ float sred[4];
    if (l == 0) sred[w] = qq;
    __syncthreads();
    float norm = sqrtf(sred[0] + sred[1] + sred[2] + sred[3]);

    float k = g_hnorm[i] * __ldg(&scale_p[0]) / fmaxf(norm, 1e-12f);
    if (g == 0) {
        const float4 xv = *(const float4*)&x[i * 128 + cbase];
        float4 ov;
        ov.x = xv.x + o0 * k;
        ov.y = xv.y + o1 * k;
        ov.z = xv.z + o2 * k;
        ov.w = xv.w + o3 * k;
        *(float4*)&out[i * 128 + cbase] = ov;
    }
}

// ---------------------------------------------------------------------------
extern "C" void kernel_launch(void* const* d_in, const int* in_sizes, int n_in,
                              void* d_out, int out_size)
{
    const float* x     = (const float*)d_in[0];
    const int*   ei    = (const int*)d_in[1];
    const float* gamma = (const float*)d_in[2];
    const float* beta  = (const float*)d_in[3];
    const float* Wl    = (const float*)d_in[4];
    const float* bl    = (const float*)d_in[5];
    const float* Wr    = (const float*)d_in[6];
    const float* br    = (const float*)d_in[7];
    const float* att   = (const float*)d_in[8];
    const float* bias  = (const float*)d_in[9];
    const float* scale = (const float*)d_in[10];
    float* out = (float*)d_out;

    int n = in_sizes[0] / 128;
    int e = in_sizes[1] / 2;
    int e2 = e + n;
    int nblk = (n + 1023) / 1024;

    ln_stats_kernel<<<n, 128>>>(x, gamma, beta, n);
    gemm_kernel<<<(n + 63) / 64, 256>>>(x, gamma, beta, Wl, bl, Wr, br, n);
    hist_kernel<<<(e2 + 255) / 256, 256>>>(ei, n, e);
    scanA_kernel<<<nblk, 1024>>>(n);
    scanC_kernel<<<nblk, 1024>>>(n, nblk);
    scatter_kernel<<<(e2 + 255) / 256, 256>>>(ei, n, e);
    gat_kernel<<<n, 128>>>(x, att, bias, scale, out, n);
}

// round 11
// speedup vs baseline: 1.5185x; 1.0707x over previous
#include <cuda_runtime.h>
#include <cuda_bf16.h>

// Problem constants: N=50000, E=800000, D=128, H=4, C=32
#define NMAX 50048
#define E2MAX 860000

__device__ float g_mu[NMAX];
__device__ float g_rstd[NMAX];
__device__ float g_hnorm[NMAX];
__device__ float g_xlr[NMAX * 256];    // [xl | xr] packed per node
__device__ int   g_count[NMAX];
__device__ int   g_rowoff[NMAX + 1];
__device__ int   g_cursor[NMAX];
__device__ int   g_csrc[E2MAX];
__device__ int   g_bsum[64];

// packed fp32x2 FMA (B300: 2 MACs/instr; exact IEEE fp32)
__device__ __forceinline__ void fma_f32x2(unsigned long long& d,
                                          unsigned long long a,
                                          unsigned long long b)
{
    asm("fma.rn.f32x2 %0, %1, %2, %0;" : "+l"(d) : "l"(a), "l"(b));
}

union U64F2 { unsigned long long u; float2 f; };

// ---------------------------------------------------------------------------
// Kernel 1: LN stats, warp-per-node (lane = 4 channels). No smem, no barriers.
// ---------------------------------------------------------------------------
__global__ __launch_bounds__(256) void ln_stats_kernel(
    const float* __restrict__ x, const float* __restrict__ gamma,
    const float* __restrict__ beta, int n)
{
    int gw = (blockIdx.x * blockDim.x + threadIdx.x) >> 5;   // node id
    int l = threadIdx.x & 31;
    if (gw >= n) return;

    float4 v = *(const float4*)&x[gw * 128 + l * 4];
    float s  = v.x + v.y + v.z + v.w;
    float s2 = v.x * v.x + v.y * v.y + v.z * v.z + v.w * v.w;
#pragma unroll
    for (int o = 16; o; o >>= 1) {
        s  += __shfl_xor_sync(0xffffffffu, s, o);
        s2 += __shfl_xor_sync(0xffffffffu, s2, o);
    }
    float mu  = s * (1.0f / 128.0f);
    float var = s2 * (1.0f / 128.0f) - mu * mu;
    float rstd = rsqrtf(var + 1e-5f);

    float4 gm = *(const float4*)&gamma[l * 4];
    float4 bt = *(const float4*)&beta[l * 4];
    float h0 = fmaxf((v.x - mu) * rstd * gm.x + bt.x, 0.f);
    float h1 = fmaxf((v.y - mu) * rstd * gm.y + bt.y, 0.f);
    float h2 = fmaxf((v.z - mu) * rstd * gm.z + bt.z, 0.f);
    float h3 = fmaxf((v.w - mu) * rstd * gm.w + bt.w, 0.f);
    float q = h0 * h0 + h1 * h1 + h2 * h2 + h3 * h3;
#pragma unroll
    for (int o = 16; o; o >>= 1) q += __shfl_xor_sync(0xffffffffu, q, o);

    if (l == 0) {
        g_mu[gw] = mu;
        g_rstd[gw] = rstd;
        g_hnorm[gw] = sqrtf(q);
        g_count[gw] = 0;
    }
}

// ---------------------------------------------------------------------------
// Kernel 2: fused LN+ReLU+SGEMM via packed f32x2 FMA.
// BM=64, BN=256, BK=32. A k-major pad 68; (a,a) packed operand built in regs.
// ---------------------------------------------------------------------------
__global__ __launch_bounds__(256) void gemm_kernel(
    const float* __restrict__ x, const float* __restrict__ gamma,
    const float* __restrict__ beta,
    const float* __restrict__ Wl, const float* __restrict__ bl,
    const float* __restrict__ Wr, const float* __restrict__ br, int n)
{
    __shared__ float As[32][68];
    __shared__ float Bs[32][256];

    int tid = threadIdx.x;
    int rowbase = blockIdx.x * 64;
    int rx = tid & 31;
    int ry = tid >> 5;

    unsigned long long acc[8][4];
#pragma unroll
    for (int r = 0; r < 8; r++)
#pragma unroll
        for (int c = 0; c < 4; c++) acc[r][c] = 0ull;

    for (int kt = 0; kt < 128; kt += 32) {
#pragma unroll
        for (int j = 0; j < 2; j++) {
            int idx = tid + j * 256;
            int row = idx >> 3;
            int q = idx & 7;
            int gr = rowbase + row;
            float4 hv = make_float4(0.f, 0.f, 0.f, 0.f);
            if (gr < n) {
                float4 v  = *(const float4*)&x[gr * 128 + kt + q * 4];
                float4 gm = *(const float4*)&gamma[kt + q * 4];
                float4 bt = *(const float4*)&beta[kt + q * 4];
                float mu = g_mu[gr], rs = g_rstd[gr];
                hv.x = fmaxf((v.x - mu) * rs * gm.x + bt.x, 0.f);
                hv.y = fmaxf((v.y - mu) * rs * gm.y + bt.y, 0.f);
                hv.z = fmaxf((v.z - mu) * rs * gm.z + bt.z, 0.f);
                hv.w = fmaxf((v.w - mu) * rs * gm.w + bt.w, 0.f);
            }
            As[q * 4 + 0][row] = hv.x;
            As[q * 4 + 1][row] = hv.y;
            As[q * 4 + 2][row] = hv.z;
            As[q * 4 + 3][row] = hv.w;
        }
#pragma unroll
        for (int j = 0; j < 8; j++) {
            int idx = tid + j * 256;
            int krow = idx >> 6;
            int col = (idx & 63) * 4;
            const float* src = (col < 128) ? &Wl[(kt + krow) * 128 + col]
                                           : &Wr[(kt + krow) * 128 + col - 128];
            *(float4*)&Bs[krow][col] = *(const float4*)src;
        }
        __syncthreads();

#pragma unroll
        for (int k = 0; k < 32; k++) {
            float a[8];
            *(float4*)&a[0] = *(float4*)&As[k][ry * 8];
            *(float4*)&a[4] = *(float4*)&As[k][ry * 8 + 4];
            ulonglong2 bq0 = *(const ulonglong2*)&Bs[k][rx * 8];
            ulonglong2 bq1 = *(const ulonglong2*)&Bs[k][rx * 8 + 4];
#pragma unroll
            for (int r = 0; r < 8; r++) {
                U64F2 ap;
                ap.f = make_float2(a[r], a[r]);
                fma_f32x2(acc[r][0], ap.u, bq0.x);
                fma_f32x2(acc[r][1], ap.u, bq0.y);
                fma_f32x2(acc[r][2], ap.u, bq1.x);
                fma_f32x2(acc[r][3], ap.u, bq1.y);
            }
        }
        __syncthreads();
    }

#pragma unroll
    for (int r = 0; r < 8; r++) {
        int gr = rowbase + ry * 8 + r;
        if (gr < n) {
#pragma unroll
            for (int c = 0; c < 8; c += 4) {
                int col = rx * 8 + c;
                const float* bb = (col < 128) ? &bl[col] : &br[col - 128];
                U64F2 p0, p1;
                p0.u = acc[r][c / 2];
                p1.u = acc[r][c / 2 + 1];
                float4 ov;
                ov.x = p0.f.x + bb[0];
                ov.y = p0.f.y + bb[1];
                ov.z = p1.f.x + bb[2];
                ov.w = p1.f.y + bb[3];
                *(float4*)&g_xlr[gr * 256 + col] = ov;
            }
        }
    }
}

// ---------------------------------------------------------------------------
// CSR build: hist -> scanA -> scanC -> scatter
// ---------------------------------------------------------------------------
__global__ void hist_kernel(const int* __restrict__ ei, int n, int e)
{
    int idx = blockIdx.x * blockDim.x + threadIdx.x;
    int e2 = e + n;
    if (idx >= e2) return;
    int d = (idx < e) ? __ldg(&ei[e + idx]) : (idx - e);
    if ((unsigned)d >= (unsigned)n) d = 0;
    atomicAdd(&g_count[d], 1);
}

__global__ __launch_bounds__(1024) void scanA_kernel(int n)
{
    __shared__ int ws[32];
    int i = blockIdx.x * 1024 + threadIdx.x;
    int t = threadIdx.x;
    int l = t & 31, w = t >> 5;
    int v = (i < n) ? g_count[i] : 0;

    int sc = v;
#pragma unroll
    for (int o = 1; o < 32; o <<= 1) {
        int u = __shfl_up_sync(0xffffffffu, sc, o);
        if (l >= o) sc += u;
    }
    if (l == 31) ws[w] = sc;
    __syncthreads();
    if (w == 0) {
        int q = (l < 32) ? ws[l] : 0;
#pragma unroll
        for (int o = 1; o < 32; o <<= 1) {
            int u = __shfl_up_sync(0xffffffffu, q, o);
            if (l >= o) q += u;
        }
        ws[l] = q;
    }
    __syncthreads();
    int excl = sc - v + (w ? ws[w - 1] : 0);
    if (i < n) g_rowoff[i] = excl;
    if (t == 1023) g_bsum[blockIdx.x] = excl + v;
}

__global__ __launch_bounds__(1024) void scanC_kernel(int n, int nblk)
{
    __shared__ int boff_sh;
    int t = threadIdx.x;
    if (t < 32) {
        int acc = 0;
        for (int b = t; b < blockIdx.x; b += 32) acc += g_bsum[b];
#pragma unroll
        for (int o = 16; o; o >>= 1) acc += __shfl_xor_sync(0xffffffffu, acc, o);
        if (t == 0) boff_sh = acc;
    }
    __syncthreads();
    int boff = boff_sh;
    int i = blockIdx.x * 1024 + t;
    if (i < n) {
        int v = g_rowoff[i] + boff;
        g_rowoff[i] = v;
        g_cursor[i] = v;
    }
    if (blockIdx.x == 0 && t < 32) {
        int tot = 0;
        for (int b = t; b < nblk; b += 32) tot += g_bsum[b];
#pragma unroll
        for (int o = 16; o; o >>= 1) tot += __shfl_xor_sync(0xffffffffu, tot, o);
        if (t == 0) g_rowoff[n] = tot;
    }
}

__global__ void scatter_kernel(const int* __restrict__ ei, int n, int e)
{
    int idx = blockIdx.x * blockDim.x + threadIdx.x;
    int e2 = e + n;
    if (idx >= e2) return;
    int s, d;
    if (idx < e) { s = __ldg(&ei[idx]); d = __ldg(&ei[e + idx]); }
    else         { s = idx - e; d = s; }
    if ((unsigned)s >= (unsigned)n) s = 0;
    if ((unsigned)d >= (unsigned)n) d = 0;
    int pos = atomicAdd(&g_cursor[d], 1);
    if (pos < E2MAX) g_csrc[pos] = s;
}

// ---------------------------------------------------------------------------
// Kernel 3: per-node GATv2, no-max softmax (exact: |score| << 88), SOFTWARE
// PIPELINED: iteration i+1's index load + feature gather issue before the
// compute of iteration i, overlapping the ~500cyc L2 chain with ~110cyc compute.
// Warp = head, lane = (edge-group g=l>>3, quad q=l&7), 4 edges/warp-iter.
// ---------------------------------------------------------------------------
__global__ __launch_bounds__(128) void gat_kernel(
    const float* __restrict__ x, const float* __restrict__ att,
    const float* __restrict__ bias, const float* __restrict__ scale_p,
    float* __restrict__ out, int n)
{
    int i = blockIdx.x;
    int t = threadIdx.x;
    int w = t >> 5;        // head
    int l = t & 31;
    int g = l >> 3;        // edge subgroup 0..3
    int q = l & 7;         // channel quad 0..7
    int cbase = w * 32 + q * 4;

    float4 xr4 = *(const float4*)&g_xlr[i * 256 + 128 + cbase];
    float4 at4 = *(const float4*)&att[cbase];
    int beg = g_rowoff[i];
    int end = g_rowoff[i + 1];   // end > beg always (self-loop)

    float s = 0.0f;
    float4 acc = make_float4(0.f, 0.f, 0.f, 0.f);

    // prologue: load edge 0 group
    int e0 = beg + g;
    bool valid = e0 < end;
    int j = g_csrc[valid ? e0 : beg];
    float4 v = *(const float4*)&g_xlr[j * 256 + cbase];

    for (int base = beg; base < end; base += 4) {
        // prefetch next iteration (safe fallback index beg)
        int en = base + 4 + g;
        bool valid_n = en < end;
        int j_n = g_csrc[valid_n ? en : beg];
        float4 v_n = *(const float4*)&g_xlr[j_n * 256 + cbase];

        // compute on current
        float z0 = v.x + xr4.x, z1 = v.y + xr4.y;
        float z2 = v.z + xr4.z, z3 = v.w + xr4.w;
        float p;
        p = at4.x * fmaxf(z0, 0.2f * z0);
        p = fmaf(at4.y, fmaxf(z1, 0.2f * z1), p);
        p = fmaf(at4.z, fmaxf(z2, 0.2f * z2), p);
        p = fmaf(at4.w, fmaxf(z3, 0.2f * z3), p);
        p += __shfl_xor_sync(0xffffffffu, p, 1);
        p += __shfl_xor_sync(0xffffffffu, p, 2);
        p += __shfl_xor_sync(0xffffffffu, p, 4);

        float wgt = valid ? __expf(p) : 0.0f;
        s += wgt;
        acc.x = fmaf(wgt, v.x, acc.x);
        acc.y = fmaf(wgt, v.y, acc.y);
        acc.z = fmaf(wgt, v.z, acc.z);
        acc.w = fmaf(wgt, v.w, acc.w);

        v = v_n;
        valid = valid_n;
    }

#pragma unroll
    for (int o = 8; o <= 16; o <<= 1) {
        s     += __shfl_xor_sync(0xffffffffu, s, o);
        acc.x += __shfl_xor_sync(0xffffffffu, acc.x, o);
        acc.y += __shfl_xor_sync(0xffffffffu, acc.y, o);
        acc.z += __shfl_xor_sync(0xffffffffu, acc.z, o);
        acc.w += __shfl_xor_sync(0xffffffffu, acc.w, o);
    }

    float inv_s = 1.0f / s;
    float4 b4 = *(const float4*)&bias[cbase];
    float o0 = acc.x * inv_s + b4.x;
    float o1 = acc.y * inv_s + b4.y;
    float o2 = acc.z * inv_s + b4.z;
    float o3 = acc.w * inv_s + b4.w;

    float qq = o0 * o0 + o1 * o1 + o2 * o2 + o3 * o3;
    qq += __shfl_xor_sync(0xffffffffu, qq, 1);
    qq += __shfl_xor_sync(0xffffffffu, qq, 2);
    qq += __shfl_xor_sync(0xffffffffu, qq, 4);
    __shared__ float sred[4];
    if (l == 0) sred[w] = qq;
    __syncthreads();
    float norm = sqrtf(sred[0] + sred[1] + sred[2] + sred[3]);

    float k = g_hnorm[i] * __ldg(&scale_p[0]) / fmaxf(norm, 1e-12f);
    if (g == 0) {
        const float4 xv = *(const float4*)&x[i * 128 + cbase];
        float4 ov;
        ov.x = xv.x + o0 * k;
        ov.y = xv.y + o1 * k;
        ov.z = xv.z + o2 * k;
        ov.w = xv.w + o3 * k;
        *(float4*)&out[i * 128 + cbase] = ov;
    }
}

// ---------------------------------------------------------------------------
extern "C" void kernel_launch(void* const* d_in, const int* in_sizes, int n_in,
                              void* d_out, int out_size)
{
    const float* x     = (const float*)d_in[0];
    const int*   ei    = (const int*)d_in[1];
    const float* gamma = (const float*)d_in[2];
    const float* beta  = (const float*)d_in[3];
    const float* Wl    = (const float*)d_in[4];
    const float* bl    = (const float*)d_in[5];
    const float* Wr    = (const float*)d_in[6];
    const float* br    = (const float*)d_in[7];
    const float* att   = (const float*)d_in[8];
    const float* bias  = (const float*)d_in[9];
    const float* scale = (const float*)d_in[10];
    float* out = (float*)d_out;

    int n = in_sizes[0] / 128;
    int e = in_sizes[1] / 2;
    int e2 = e + n;
    int nblk = (n + 1023) / 1024;

    ln_stats_kernel<<<(n * 32 + 255) / 256, 256>>>(x, gamma, beta, n);
    gemm_kernel<<<(n + 63) / 64, 256>>>(x, gamma, beta, Wl, bl, Wr, br, n);
    hist_kernel<<<(e2 + 255) / 256, 256>>>(ei, n, e);
    scanA_kernel<<<nblk, 1024>>>(n);
    scanC_kernel<<<nblk, 1024>>>(n, nblk);
    scatter_kernel<<<(e2 + 255) / 256, 256>>>(ei, n, e);
    gat_kernel<<<n, 128>>>(x, att, bias, scale, out, n);
}